// round 5
// baseline (speedup 1.0000x reference)
#include <cuda_runtime.h>

#define NB 48
#define NL 17
#define ND 256
#define NM 768    /* NB*(NL-1) */
#define NR 832    /* NM + NB anchors = 13*64, tile-exact */
#define KSPLIT 4
#define PAIR_BLOCKS 768

__device__ float g_all [NR*ND];         // rows 0..767 toks, 768..815 anchors, 816..831 zero
__device__ float g_sp  [KSPLIT][NR*NM]; // split-K partials of all @ toks^T
__device__ float g_E   [NR*NM];         // exp(sims): rows 0..767 = Et, 768..815 = Ea
__device__ float g_c   [NB];            // 1 / sum_neg exp(s_anc)
__device__ float g_kl  [NB*NM];
__device__ float g_row [NB];
__device__ float g_nneg[NB];
__device__ int   g_lab [NB];
__device__ int   g_np;
__device__ int   g_pairs[NB*NM];        // (b<<16)|j, grouped by b

// ---------------------------------------------------------------- utilities
__device__ __forceinline__ float blockReduceSum(float v, volatile float* sm) {
    int lane = threadIdx.x & 31, wid = threadIdx.x >> 5;
    #pragma unroll
    for (int o = 16; o > 0; o >>= 1) v += __shfl_down_sync(0xffffffffu, v, o);
    if (lane == 0) sm[wid] = v;
    __syncthreads();
    if (threadIdx.x < 32) {
        float r = (threadIdx.x < 8) ? sm[threadIdx.x] : 0.f;
        #pragma unroll
        for (int o = 4; o > 0; o >>= 1) r += __shfl_down_sync(0xffffffffu, r, o);
        if (threadIdx.x == 0) sm[0] = r;
    }
    __syncthreads();
    float r = sm[0];
    __syncthreads();
    return r;
}

// ---------------- 0: labels (dtype sniff) + counts + compacted pair list
// Reference declares int64 labels; jax w/o x64 silently yields int32. An
// int64 buffer (values 0..7, little-endian) read as int32 is [v,0,v,0,...].
__global__ void k_setup(const int* __restrict__ lab32) {
    __shared__ int lab[NB];
    __shared__ int base[NB];
    __shared__ int wc[8];
    __shared__ int is64s;
    int t = threadIdx.x, lane = t & 31, w = t >> 5;
    if (t == 0) {
        bool is64 = true;
        for (int i = 1; i < NB; i += 2) if (lab32[i] != 0) { is64 = false; break; }
        if (is64) for (int i = 0; i < NB; i += 2) {
            int v = lab32[i];
            if (v < 0 || v >= 8) { is64 = false; break; }
        }
        is64s = is64 ? 1 : 0;
    }
    __syncthreads();
    if (t < NB) lab[t] = is64s ? (int)((const long long*)lab32)[t] : lab32[t];
    __syncthreads();
    if (t < NB) {
        int same = 0;
        #pragma unroll 8
        for (int o = 0; o < NB; o++) same += (lab[o] == lab[t]) ? 1 : 0;
        g_nneg[t] = (float)((NB - same) * (NL - 1));
        g_lab[t]  = lab[t];
    }
    if (t == 0) {
        int s = 0;
        for (int b = 0; b < NB; b++) {
            int same = 0;
            for (int o = 0; o < NB; o++) same += (lab[o] == lab[b]) ? 1 : 0;
            base[b] = s; s += same * (NL - 1);
        }
        g_np = s;
    }
    __syncthreads();
    for (int b = 0; b < NB; b++) {
        int mb = lab[b];
        int bb = base[b];
        #pragma unroll
        for (int q = 0; q < 3; q++) {
            int j = q * 256 + t;
            bool act = (lab[j >> 4] == mb);
            unsigned bal = __ballot_sync(0xffffffffu, act);
            if (lane == 0) wc[w] = __popc(bal);
            __syncthreads();
            int off = 0, tot = 0;
            #pragma unroll
            for (int i = 0; i < 8; i++) { int v = wc[i]; if (i < w) off += v; tot += v; }
            if (act) g_pairs[bb + off + __popc(bal & ((1u << lane) - 1u))] = (b << 16) | j;
            bb += tot;
            __syncthreads();
        }
    }
}

// --------------------------------------- 1: normalize rows into g_all
__global__ void k_norm(const float* __restrict__ x) {
    __shared__ float red[32];
    int r = blockIdx.x, d = threadIdx.x;
    if (r >= NB * NL) {                 // zero pad rows 816..831
        g_all[(NM + r - NB * NL + NB) * ND + d] = 0.f;
        return;
    }
    float v = x[r * ND + d];
    float ss = blockReduceSum(v * v, red);
    float inv = 1.f / fmaxf(sqrtf(ss), 1e-12f);
    float xn = v * inv;
    int b = r / NL, p = r - b * NL;
    int row = (p == 0) ? (NM + b) : (b * (NL - 1) + p - 1);
    g_all[row * ND + d] = xn;
}

// ----------- 2a: split-K GEMM partials of all @ toks^T (vectorized smem)
__global__ void k_gemm(void) {
    __shared__ __align__(16) float AsT[32][68];   // [k][row], stride 68 keeps f4 align
    __shared__ __align__(16) float BsT[32][68];
    int t = threadIdx.x, tx = t & 15, ty = t >> 4;
    int kb = blockIdx.x * 64, jb = blockIdx.y * 64, z = blockIdx.z;
    float acc[4][4] = {};
    int kbeg = z * (ND / KSPLIT), kend = kbeg + ND / KSPLIT;
    for (int k0 = kbeg; k0 < kend; k0 += 32) {
        #pragma unroll
        for (int u = 0; u < 2; u++) {
            int i = t + u * 256;            // 512 float4 slots: 64 rows x 8
            int row = i >> 3, c4 = (i & 7) * 4;
            float4 v = *(const float4*)&g_all[(jb + row) * ND + k0 + c4];
            AsT[c4+0][row] = v.x; AsT[c4+1][row] = v.y;
            AsT[c4+2][row] = v.z; AsT[c4+3][row] = v.w;
            float4 u4 = *(const float4*)&g_all[(kb + row) * ND + k0 + c4];
            BsT[c4+0][row] = u4.x; BsT[c4+1][row] = u4.y;
            BsT[c4+2][row] = u4.z; BsT[c4+3][row] = u4.w;
        }
        __syncthreads();
        #pragma unroll
        for (int dd = 0; dd < 32; dd++) {
            float4 av = *(const float4*)&AsT[dd][ty * 4];
            float4 bv = *(const float4*)&BsT[dd][tx * 4];
            acc[0][0] = fmaf(av.x, bv.x, acc[0][0]); acc[0][1] = fmaf(av.x, bv.y, acc[0][1]);
            acc[0][2] = fmaf(av.x, bv.z, acc[0][2]); acc[0][3] = fmaf(av.x, bv.w, acc[0][3]);
            acc[1][0] = fmaf(av.y, bv.x, acc[1][0]); acc[1][1] = fmaf(av.y, bv.y, acc[1][1]);
            acc[1][2] = fmaf(av.y, bv.z, acc[1][2]); acc[1][3] = fmaf(av.y, bv.w, acc[1][3]);
            acc[2][0] = fmaf(av.z, bv.x, acc[2][0]); acc[2][1] = fmaf(av.z, bv.y, acc[2][1]);
            acc[2][2] = fmaf(av.z, bv.z, acc[2][2]); acc[2][3] = fmaf(av.z, bv.w, acc[2][3]);
            acc[3][0] = fmaf(av.w, bv.x, acc[3][0]); acc[3][1] = fmaf(av.w, bv.y, acc[3][1]);
            acc[3][2] = fmaf(av.w, bv.z, acc[3][2]); acc[3][3] = fmaf(av.w, bv.w, acc[3][3]);
        }
        __syncthreads();
    }
    #pragma unroll
    for (int i = 0; i < 4; i++) {
        float4 r = make_float4(acc[i][0], acc[i][1], acc[i][2], acc[i][3]);
        *(float4*)&g_sp[z][(jb + ty * 4 + i) * NM + kb + tx * 4] = r;
    }
}

// -------------------------- 2b: combine split-K partials, apply exp
__global__ void k_combine(void) {
    int i = blockIdx.x * 256 + threadIdx.x;      // float4 index over NR*NM/4
    const float4* p0 = (const float4*)g_sp[0];
    const float4* p1 = (const float4*)g_sp[1];
    const float4* p2 = (const float4*)g_sp[2];
    const float4* p3 = (const float4*)g_sp[3];
    float4 a = p0[i], b = p1[i], c = p2[i], d = p3[i];
    float4 r;
    r.x = expf((a.x + b.x) + (c.x + d.x));
    r.y = expf((a.y + b.y) + (c.y + d.y));
    r.z = expf((a.z + b.z) + (c.z + d.z));
    r.w = expf((a.w + b.w) + (c.w + d.w));
    ((float4*)g_E)[i] = r;
}

// -------------------------- 2c: c[b] = 1 / sum_neg Ea[b,k]
__global__ void k_c(void) {
    __shared__ int lab[NB];
    __shared__ float red[32];
    int b = blockIdx.x, t = threadIdx.x;
    if (t < NB) lab[t] = g_lab[t];
    __syncthreads();
    int mb = lab[b];
    const float* Ea = g_E + (NM + b) * NM;
    float p = 0.f;
    #pragma unroll
    for (int q = 0; q < 3; q++) {
        int k = q * 256 + t;
        if (lab[k >> 4] != mb) p += Ea[k];
    }
    float P = blockReduceSum(p, red);
    if (t == 0) g_c[b] = 1.f / P;
}

// ------------------- 3: warp-per-pair symmetric KL (cancellation-free)
// e=c*Et, a=c*Ea, t=e-a, mu=exp(e)-1 (series), d=mu-nu=t*h (series)
// symKL = 0.5*(Sdt*D1 - Sd*N1)/(D1*D2); D1=n+Smu, N1=St+Smut, D2=D1-Sd
__global__ void k_pairs(void) {
    __shared__ int lab[NB];
    int t = threadIdx.x, lane = t & 31, w = t >> 5;
    if (t < NB) lab[t] = g_lab[t];
    __syncthreads();
    int np = g_np;
    for (int p = blockIdx.x * 8 + w; p < np; p += PAIR_BLOCKS * 8) {
        int pr = g_pairs[p];
        int b = pr >> 16, j = pr & 0xffff;
        int mb = lab[b];
        float c = g_c[b];
        const float* Et = g_E + j * NM;
        const float* Ea = g_E + (NM + b) * NM;

        float s0 = 0.f, s1 = 0.f, s2 = 0.f, s3 = 0.f, s4 = 0.f;
        #pragma unroll 4
        for (int i = 0; i < NM / 32; i++) {
            int k = i * 32 + lane;
            float m  = (lab[k >> 4] != mb) ? c : 0.f;   // zeroed lanes give 0 terms
            float e  = m * Et[k];
            float a  = m * Ea[k];
            float tt = e - a;
            float mu = e * (1.f + e * (0.5f + e * (1.f/6.f + e * (1.f/24.f))));
            float sp = e + a;
            float e2 = e * e, ea = e * a, a2 = a * a;
            float h  = 1.f + 0.5f * sp + (e2 + ea + a2) * (1.f/6.f)
                     + sp * (e2 + a2) * (1.f/24.f);
            float d  = tt * h;
            s0 += tt; s1 += mu; s2 = fmaf(mu, tt, s2);
            s3 += d;  s4 = fmaf(tt, d, s4);
        }
        #pragma unroll
        for (int o = 16; o > 0; o >>= 1) {
            s0 += __shfl_down_sync(0xffffffffu, s0, o);
            s1 += __shfl_down_sync(0xffffffffu, s1, o);
            s2 += __shfl_down_sync(0xffffffffu, s2, o);
            s3 += __shfl_down_sync(0xffffffffu, s3, o);
            s4 += __shfl_down_sync(0xffffffffu, s4, o);
        }
        if (lane == 0) {
            float n  = g_nneg[b];
            float D1 = n + s1;
            float N1 = s0 + s2;
            float D2 = D1 - s3;
            float num = s4 * D1 - s3 * N1;
            g_kl[b * NM + j] = 0.5f * num / (D1 * D2);
        }
    }
}

// ------------------------------------- 4a: per-b row mean (block per b)
__global__ void k_final1(void) {
    __shared__ int lab[NB];
    __shared__ float red[32];
    int b = blockIdx.x, t = threadIdx.x;
    if (t < NB) lab[t] = g_lab[t];
    __syncthreads();
    int mb = lab[b];
    float rs = 0.f, cnt = 0.f;
    #pragma unroll
    for (int q = 0; q < 3; q++) {
        int j = q * 256 + t;
        if (lab[j >> 4] == mb) { rs += g_kl[b * NM + j]; cnt += 1.f; }
    }
    float rowsum = blockReduceSum(rs, red);
    float P      = blockReduceSum(cnt, red);
    if (t == 0) g_row[b] = rowsum / P;
}

// ------------------------------------- 4b: deterministic 48-element reduce
__global__ void k_final2(float* __restrict__ out) {
    __shared__ float v[NB];
    int t = threadIdx.x;
    if (t < NB) v[t] = g_row[t];
    __syncthreads();
    if (t == 0) {
        float s = 0.f;
        for (int b = 0; b < NB; b++) s += v[b];
        out[0] = s / (float)NB;
    }
}

// ----------------------------------------------------------------- launch
extern "C" void kernel_launch(void* const* d_in, const int* in_sizes, int n_in,
                              void* d_out, int out_size) {
    const float* x     = (const float*)d_in[0];
    const int*   lab32 = (const int*)  d_in[1];
    float*       out   = (float*)      d_out;
    (void)in_sizes; (void)n_in; (void)out_size;

    k_setup  <<<1, 256>>>(lab32);
    k_norm   <<<NR, 256>>>(x);
    k_gemm   <<<dim3(NM / 64, NR / 64, KSPLIT), 256>>>();
    k_combine<<<NR * NM / 4 / 256, 256>>>();
    k_c      <<<NB, 256>>>();
    k_pairs  <<<PAIR_BLOCKS, 256>>>();
    k_final1 <<<NB, 256>>>();
    k_final2 <<<1, 64>>>(out);
}

// round 6
// speedup vs baseline: 1.0607x; 1.0607x over previous
#include <cuda_runtime.h>

#define NB 48
#define NL 17
#define ND 256
#define NM 768    /* NB*(NL-1) */
#define NR 832    /* NM + NB anchors = 13*64 */
#define PAIR_BLOCKS 768
#define NTILES 90 /* 78 upper-tri tok tiles + 12 anchor-row tiles */

__device__ float g_all [NR*ND];   // rows 0..767 toks, 768..815 anchors, 816..831 zero
__device__ float g_E   [NR*NM];   // exp(sims): rows 0..767 Et (symmetric), 768..815 Ea
__device__ float g_c   [NB];      // 1 / sum_neg exp(s_anc)
__device__ float g_kl  [NB*NM];
__device__ float g_row [NB];
__device__ float g_nneg[NB];
__device__ int   g_lab [NB];
__device__ int   g_np;
__device__ int   g_pairs[NB*NM];  // (b<<16)|j, grouped by b

// ---------------------------------------------------------------- utilities
__device__ __forceinline__ float blockReduceSum(float v, volatile float* sm) {
    int lane = threadIdx.x & 31, wid = threadIdx.x >> 5;
    #pragma unroll
    for (int o = 16; o > 0; o >>= 1) v += __shfl_down_sync(0xffffffffu, v, o);
    if (lane == 0) sm[wid] = v;
    __syncthreads();
    if (threadIdx.x < 32) {
        float r = (threadIdx.x < 8) ? sm[threadIdx.x] : 0.f;
        #pragma unroll
        for (int o = 4; o > 0; o >>= 1) r += __shfl_down_sync(0xffffffffu, r, o);
        if (threadIdx.x == 0) sm[0] = r;
    }
    __syncthreads();
    float r = sm[0];
    __syncthreads();
    return r;
}

// ---------------- 0: labels (dtype sniff) + counts + compacted pair list
// Reference declares int64 labels; jax w/o x64 silently yields int32. An
// int64 buffer (values 0..7, little-endian) read as int32 is [v,0,v,0,...].
__global__ void k_setup(const int* __restrict__ lab32) {
    __shared__ int lab[NB];
    __shared__ int base[NB];
    __shared__ int wc[8];
    __shared__ int is64s;
    int t = threadIdx.x, lane = t & 31, w = t >> 5;
    if (t == 0) {
        bool is64 = true;
        for (int i = 1; i < NB; i += 2) if (lab32[i] != 0) { is64 = false; break; }
        if (is64) for (int i = 0; i < NB; i += 2) {
            int v = lab32[i];
            if (v < 0 || v >= 8) { is64 = false; break; }
        }
        is64s = is64 ? 1 : 0;
    }
    __syncthreads();
    if (t < NB) lab[t] = is64s ? (int)((const long long*)lab32)[t] : lab32[t];
    __syncthreads();
    if (t < NB) {
        int same = 0;
        #pragma unroll 8
        for (int o = 0; o < NB; o++) same += (lab[o] == lab[t]) ? 1 : 0;
        g_nneg[t] = (float)((NB - same) * (NL - 1));
        g_lab[t]  = lab[t];
    }
    if (t == 0) {
        int s = 0;
        for (int b = 0; b < NB; b++) {
            int same = 0;
            for (int o = 0; o < NB; o++) same += (lab[o] == lab[b]) ? 1 : 0;
            base[b] = s; s += same * (NL - 1);
        }
        g_np = s;
    }
    __syncthreads();
    for (int b = 0; b < NB; b++) {
        int mb = lab[b];
        int bb = base[b];
        #pragma unroll
        for (int q = 0; q < 3; q++) {
            int j = q * 256 + t;
            bool act = (lab[j >> 4] == mb);
            unsigned bal = __ballot_sync(0xffffffffu, act);
            if (lane == 0) wc[w] = __popc(bal);
            __syncthreads();
            int off = 0, tot = 0;
            #pragma unroll
            for (int i = 0; i < 8; i++) { int v = wc[i]; if (i < w) off += v; tot += v; }
            if (act) g_pairs[bb + off + __popc(bal & ((1u << lane) - 1u))] = (b << 16) | j;
            bb += tot;
            __syncthreads();
        }
    }
}

// --------------------------------------- 1: normalize rows into g_all
__global__ void k_norm(const float* __restrict__ x) {
    __shared__ float red[32];
    int r = blockIdx.x, d = threadIdx.x;
    if (r >= NB * NL) {                 // zero pad rows 816..831
        g_all[(NM + r - NB * NL + NB) * ND + d] = 0.f;
        return;
    }
    float v = x[r * ND + d];
    float ss = blockReduceSum(v * v, red);
    float inv = 1.f / fmaxf(sqrtf(ss), 1e-12f);
    float xn = v * inv;
    int b = r / NL, p = r - b * NL;
    int row = (p == 0) ? (NM + b) : (b * (NL - 1) + p - 1);
    g_all[row * ND + d] = xn;
}

// --------- 2: symmetric GEMM, exp epilogue, mirror write for off-diag tiles
// tiles: id 0..77 -> (jt,kt) upper triangle of 12x12 tok grid; 78..89 -> (12,kt)
__global__ void k_gemm(void) {
    __shared__ float sbuf[2 * 64 * 33];
    float* As = sbuf;                 // [64][33]
    float* Bs = sbuf + 64 * 33;
    int t = threadIdx.x, tx = t & 15, ty = t >> 4;

    int id = blockIdx.x, jt, kt;
    if (id < 78) {
        jt = 0; int rem = id;
        while (rem >= 12 - jt) { rem -= 12 - jt; jt++; }
        kt = jt + rem;
    } else { jt = 12; kt = id - 78; }
    int jb = jt * 64, kb = kt * 64;

    // register prefetch of chunk 0
    float4 pa[2], pb[2];
    #pragma unroll
    for (int u = 0; u < 2; u++) {
        int idx = t + u * 256, row = idx >> 3, c4 = (idx & 7) * 4;
        pa[u] = *(const float4*)&g_all[(jb + row) * ND + c4];
        pb[u] = *(const float4*)&g_all[(kb + row) * ND + c4];
    }

    float acc[4][4] = {};
    for (int ch = 0; ch < 8; ch++) {
        __syncthreads();
        #pragma unroll
        for (int u = 0; u < 2; u++) {
            int idx = t + u * 256, row = idx >> 3, c4 = (idx & 7) * 4;
            As[row * 33 + c4 + 0] = pa[u].x; As[row * 33 + c4 + 1] = pa[u].y;
            As[row * 33 + c4 + 2] = pa[u].z; As[row * 33 + c4 + 3] = pa[u].w;
            Bs[row * 33 + c4 + 0] = pb[u].x; Bs[row * 33 + c4 + 1] = pb[u].y;
            Bs[row * 33 + c4 + 2] = pb[u].z; Bs[row * 33 + c4 + 3] = pb[u].w;
        }
        __syncthreads();
        if (ch < 7) {
            int k0 = (ch + 1) * 32;
            #pragma unroll
            for (int u = 0; u < 2; u++) {
                int idx = t + u * 256, row = idx >> 3, c4 = (idx & 7) * 4;
                pa[u] = *(const float4*)&g_all[(jb + row) * ND + k0 + c4];
                pb[u] = *(const float4*)&g_all[(kb + row) * ND + k0 + c4];
            }
        }
        #pragma unroll
        for (int dd = 0; dd < 32; dd++) {
            float a0 = As[(ty*4+0)*33 + dd], a1 = As[(ty*4+1)*33 + dd],
                  a2 = As[(ty*4+2)*33 + dd], a3 = As[(ty*4+3)*33 + dd];
            float b0 = Bs[(tx*4+0)*33 + dd], b1 = Bs[(tx*4+1)*33 + dd],
                  b2 = Bs[(tx*4+2)*33 + dd], b3 = Bs[(tx*4+3)*33 + dd];
            acc[0][0] = fmaf(a0,b0,acc[0][0]); acc[0][1] = fmaf(a0,b1,acc[0][1]);
            acc[0][2] = fmaf(a0,b2,acc[0][2]); acc[0][3] = fmaf(a0,b3,acc[0][3]);
            acc[1][0] = fmaf(a1,b0,acc[1][0]); acc[1][1] = fmaf(a1,b1,acc[1][1]);
            acc[1][2] = fmaf(a1,b2,acc[1][2]); acc[1][3] = fmaf(a1,b3,acc[1][3]);
            acc[2][0] = fmaf(a2,b0,acc[2][0]); acc[2][1] = fmaf(a2,b1,acc[2][1]);
            acc[2][2] = fmaf(a2,b2,acc[2][2]); acc[2][3] = fmaf(a2,b3,acc[2][3]);
            acc[3][0] = fmaf(a3,b0,acc[3][0]); acc[3][1] = fmaf(a3,b1,acc[3][1]);
            acc[3][2] = fmaf(a3,b2,acc[3][2]); acc[3][3] = fmaf(a3,b3,acc[3][3]);
        }
    }

    // exp + direct coalesced write
    float er[4][4];
    #pragma unroll
    for (int i = 0; i < 4; i++) {
        er[i][0] = expf(acc[i][0]); er[i][1] = expf(acc[i][1]);
        er[i][2] = expf(acc[i][2]); er[i][3] = expf(acc[i][3]);
        float4 r = make_float4(er[i][0], er[i][1], er[i][2], er[i][3]);
        *(float4*)&g_E[(jb + ty * 4 + i) * NM + kb + tx * 4] = r;
    }

    // mirror write for off-diagonal tok tiles via smem transpose (stride 65)
    if (jt < 12 && jt != kt) {
        __syncthreads();                 // done with As/Bs
        float* Tr = sbuf;                // 64*65 = 4160 <= 4224 floats
        #pragma unroll
        for (int i = 0; i < 4; i++)
            #pragma unroll
            for (int l = 0; l < 4; l++)
                Tr[(tx * 4 + l) * 65 + ty * 4 + i] = er[i][l];
        __syncthreads();
        #pragma unroll
        for (int u = 0; u < 4; u++) {
            int idx = t + u * 256;       // 1024 float4 = 64 rows x 16
            int r = idx >> 4, c4 = (idx & 15) * 4;
            float4 v = make_float4(Tr[r*65 + c4], Tr[r*65 + c4 + 1],
                                   Tr[r*65 + c4 + 2], Tr[r*65 + c4 + 3]);
            *(float4*)&g_E[(kb + r) * NM + jb + c4] = v;
        }
    }
}

// -------------------------- 3: c[b] = 1 / sum_neg Ea[b,k]
__global__ void k_c(void) {
    __shared__ int lab[NB];
    __shared__ float red[32];
    int b = blockIdx.x, t = threadIdx.x;
    if (t < NB) lab[t] = g_lab[t];
    __syncthreads();
    int mb = lab[b];
    const float* Ea = g_E + (NM + b) * NM;
    float p = 0.f;
    #pragma unroll
    for (int q = 0; q < 3; q++) {
        int k = q * 256 + t;
        if (lab[k >> 4] != mb) p += Ea[k];
    }
    float P = blockReduceSum(p, red);
    if (t == 0) g_c[b] = 1.f / P;
}

// ------------------- 4: warp-per-pair symmetric KL (cancellation-free)
// e=c*Et, a=c*Ea, t=e-a, mu=exp(e)-1 (series), d=mu-nu=t*h (series)
// symKL = 0.5*(Sdt*D1 - Sd*N1)/(D1*D2); D1=n+Smu, N1=St+Smut, D2=D1-Sd
__global__ void k_pairs(void) {
    __shared__ int lab[NB];
    int t = threadIdx.x, lane = t & 31, w = t >> 5;
    if (t < NB) lab[t] = g_lab[t];
    __syncthreads();
    int np = g_np;
    for (int p = blockIdx.x * 8 + w; p < np; p += PAIR_BLOCKS * 8) {
        int pr = g_pairs[p];
        int b = pr >> 16, j = pr & 0xffff;
        int mb = lab[b];
        float c = g_c[b];
        const float* Et = g_E + j * NM;
        const float* Ea = g_E + (NM + b) * NM;

        float s0 = 0.f, s1 = 0.f, s2 = 0.f, s3 = 0.f, s4 = 0.f;
        #pragma unroll 4
        for (int i = 0; i < NM / 32; i++) {
            int k = i * 32 + lane;
            float m  = (lab[k >> 4] != mb) ? c : 0.f;   // zeroed lanes give 0 terms
            float e  = m * Et[k];
            float a  = m * Ea[k];
            float tt = e - a;
            float mu = e * (1.f + e * (0.5f + e * (1.f/6.f + e * (1.f/24.f))));
            float sp = e + a;
            float e2 = e * e, ea = e * a, a2 = a * a;
            float h  = 1.f + 0.5f * sp + (e2 + ea + a2) * (1.f/6.f)
                     + sp * (e2 + a2) * (1.f/24.f);
            float d  = tt * h;
            s0 += tt; s1 += mu; s2 = fmaf(mu, tt, s2);
            s3 += d;  s4 = fmaf(tt, d, s4);
        }
        #pragma unroll
        for (int o = 16; o > 0; o >>= 1) {
            s0 += __shfl_down_sync(0xffffffffu, s0, o);
            s1 += __shfl_down_sync(0xffffffffu, s1, o);
            s2 += __shfl_down_sync(0xffffffffu, s2, o);
            s3 += __shfl_down_sync(0xffffffffu, s3, o);
            s4 += __shfl_down_sync(0xffffffffu, s4, o);
        }
        if (lane == 0) {
            float n  = g_nneg[b];
            float D1 = n + s1;
            float N1 = s0 + s2;
            float D2 = D1 - s3;
            float num = s4 * D1 - s3 * N1;
            g_kl[b * NM + j] = 0.5f * num / (D1 * D2);
        }
    }
}

// ------------------------------------- 5a: per-b row mean (block per b)
__global__ void k_final1(void) {
    __shared__ int lab[NB];
    __shared__ float red[32];
    int b = blockIdx.x, t = threadIdx.x;
    if (t < NB) lab[t] = g_lab[t];
    __syncthreads();
    int mb = lab[b];
    float rs = 0.f, cnt = 0.f;
    #pragma unroll
    for (int q = 0; q < 3; q++) {
        int j = q * 256 + t;
        if (lab[j >> 4] == mb) { rs += g_kl[b * NM + j]; cnt += 1.f; }
    }
    float rowsum = blockReduceSum(rs, red);
    float P      = blockReduceSum(cnt, red);
    if (t == 0) g_row[b] = rowsum / P;
}

// ------------------------------------- 5b: deterministic 48-element reduce
__global__ void k_final2(float* __restrict__ out) {
    __shared__ float v[NB];
    int t = threadIdx.x;
    if (t < NB) v[t] = g_row[t];
    __syncthreads();
    if (t == 0) {
        float s = 0.f;
        for (int b = 0; b < NB; b++) s += v[b];
        out[0] = s / (float)NB;
    }
}

// ----------------------------------------------------------------- launch
extern "C" void kernel_launch(void* const* d_in, const int* in_sizes, int n_in,
                              void* d_out, int out_size) {
    const float* x     = (const float*)d_in[0];
    const int*   lab32 = (const int*)  d_in[1];
    float*       out   = (float*)      d_out;
    (void)in_sizes; (void)n_in; (void)out_size;

    k_setup  <<<1, 256>>>(lab32);
    k_norm   <<<NR, 256>>>(x);
    k_gemm   <<<NTILES, 256>>>();
    k_c      <<<NB, 256>>>();
    k_pairs  <<<PAIR_BLOCKS, 256>>>();
    k_final1 <<<NB, 256>>>();
    k_final2 <<<1, 64>>>(out);
}

// round 7
// speedup vs baseline: 1.0656x; 1.0046x over previous
#include <cuda_runtime.h>

#define NB 48
#define NL 17
#define ND 256
#define NM 768    /* NB*(L-1) */
#define NR 832    /* NM + NB anchors = 13*64 */
#define PAIR_BLOCKS 768
#define NTILES 90 /* 78 upper-tri tok tiles + 12 anchor-row tiles */

#define SCALE_C  4294967296.0f           /* 2^32 for csum fixed-point */
#define SCALE_KL 1.125899906842624e15f   /* 2^50 for kl fixed-point */

__device__ float g_all [NR*ND];   // rows 0..767 toks, 768..815 anchors, 816..831 zero
__device__ float g_E   [NR*NM];   // exp(sims): rows 0..767 Et (symmetric), 768..815 Ea
__device__ float g_nneg[NB];
__device__ float g_P   [NB];
__device__ int   g_lab [NB];
__device__ int   g_np;
__device__ int   g_pairs[NB*NM];  // (b<<16)|j, grouped by b
__device__ unsigned long long g_csum  [NB];  // sum_neg Ea[b,k] * 2^32
__device__ unsigned long long g_rowsum[NB];  // sum_j kl[b,j]   * 2^50
__device__ unsigned int       g_done;

// ---------------------------------------------------------------- utilities
__device__ __forceinline__ float blockReduceSum(float v, volatile float* sm) {
    int lane = threadIdx.x & 31, wid = threadIdx.x >> 5;
    #pragma unroll
    for (int o = 16; o > 0; o >>= 1) v += __shfl_down_sync(0xffffffffu, v, o);
    if (lane == 0) sm[wid] = v;
    __syncthreads();
    if (threadIdx.x < 32) {
        float r = (threadIdx.x < 8) ? sm[threadIdx.x] : 0.f;
        #pragma unroll
        for (int o = 4; o > 0; o >>= 1) r += __shfl_down_sync(0xffffffffu, r, o);
        if (threadIdx.x == 0) sm[0] = r;
    }
    __syncthreads();
    float r = sm[0];
    __syncthreads();
    return r;
}

// ------------- 0: fused prep. block 0: labels+plan+zero accums; 1..832: norm
// Reference declares int64 labels; jax w/o x64 silently yields int32. An
// int64 buffer (values 0..7, little-endian) read as int32 is [v,0,v,0,...].
__global__ void k_prep(const float* __restrict__ x, const int* __restrict__ lab32) {
    int t = threadIdx.x;
    if (blockIdx.x == 0) {
        __shared__ int lab[NB];
        __shared__ int base[NB];
        __shared__ int wc[8];
        __shared__ int is64s;
        int lane = t & 31, w = t >> 5;
        if (t == 0) {
            bool is64 = true;
            for (int i = 1; i < NB; i += 2) if (lab32[i] != 0) { is64 = false; break; }
            if (is64) for (int i = 0; i < NB; i += 2) {
                int v = lab32[i];
                if (v < 0 || v >= 8) { is64 = false; break; }
            }
            is64s = is64 ? 1 : 0;
            g_done = 0u;
        }
        __syncthreads();
        if (t < NB) {
            lab[t] = is64s ? (int)((const long long*)lab32)[t] : lab32[t];
            g_csum[t] = 0ull;
            g_rowsum[t] = 0ull;
        }
        __syncthreads();
        if (t < NB) {
            int same = 0;
            #pragma unroll 8
            for (int o = 0; o < NB; o++) same += (lab[o] == lab[t]) ? 1 : 0;
            g_nneg[t] = (float)((NB - same) * (NL - 1));
            g_P[t]    = (float)(same * (NL - 1));
            g_lab[t]  = lab[t];
        }
        if (t == 0) {
            int s = 0;
            for (int b = 0; b < NB; b++) {
                int same = 0;
                for (int o = 0; o < NB; o++) same += (lab[o] == lab[b]) ? 1 : 0;
                base[b] = s; s += same * (NL - 1);
            }
            g_np = s;
        }
        __syncthreads();
        for (int b = 0; b < NB; b++) {
            int mb = lab[b];
            int bb = base[b];
            #pragma unroll
            for (int q = 0; q < 3; q++) {
                int j = q * 256 + t;
                bool act = (lab[j >> 4] == mb);
                unsigned bal = __ballot_sync(0xffffffffu, act);
                if (lane == 0) wc[w] = __popc(bal);
                __syncthreads();
                int off = 0, tot = 0;
                #pragma unroll
                for (int i = 0; i < 8; i++) { int v = wc[i]; if (i < w) off += v; tot += v; }
                if (act) g_pairs[bb + off + __popc(bal & ((1u << lane) - 1u))] = (b << 16) | j;
                bb += tot;
                __syncthreads();
            }
        }
        return;
    }
    // normalize rows
    __shared__ float red[32];
    int r = blockIdx.x - 1, d = t;
    if (r >= NB * NL) {                 // zero pad rows 816..831
        g_all[(NM + r - NB * NL + NB) * ND + d] = 0.f;
        return;
    }
    float v = x[r * ND + d];
    float ss = blockReduceSum(v * v, red);
    float inv = 1.f / fmaxf(sqrtf(ss), 1e-12f);
    float xn = v * inv;
    int b = r / NL, p = r - b * NL;
    int row = (p == 0) ? (NM + b) : (b * (NL - 1) + p - 1);
    g_all[row * ND + d] = xn;
}

// --------- 1: symmetric GEMM, exp epilogue, mirror write for off-diag tiles,
//              fused csum accumulation on anchor-row tiles (jt==12)
// tiles: id 0..77 -> (jt,kt) upper triangle of 12x12 tok grid; 78..89 -> (12,kt)
__global__ void k_gemm(void) {
    __shared__ float sbuf[2 * 64 * 33];
    __shared__ int lab[NB];
    float* As = sbuf;                 // [64][33]
    float* Bs = sbuf + 64 * 33;
    int t = threadIdx.x, tx = t & 15, ty = t >> 4;
    if (t < NB) lab[t] = g_lab[t];

    int id = blockIdx.x, jt, kt;
    if (id < 78) {
        jt = 0; int rem = id;
        while (rem >= 12 - jt) { rem -= 12 - jt; jt++; }
        kt = jt + rem;
    } else { jt = 12; kt = id - 78; }
    int jb = jt * 64, kb = kt * 64;

    // register prefetch of chunk 0
    float4 pa[2], pb[2];
    #pragma unroll
    for (int u = 0; u < 2; u++) {
        int idx = t + u * 256, row = idx >> 3, c4 = (idx & 7) * 4;
        pa[u] = *(const float4*)&g_all[(jb + row) * ND + c4];
        pb[u] = *(const float4*)&g_all[(kb + row) * ND + c4];
    }

    float acc[4][4] = {};
    for (int ch = 0; ch < 8; ch++) {
        __syncthreads();
        #pragma unroll
        for (int u = 0; u < 2; u++) {
            int idx = t + u * 256, row = idx >> 3, c4 = (idx & 7) * 4;
            As[row * 33 + c4 + 0] = pa[u].x; As[row * 33 + c4 + 1] = pa[u].y;
            As[row * 33 + c4 + 2] = pa[u].z; As[row * 33 + c4 + 3] = pa[u].w;
            Bs[row * 33 + c4 + 0] = pb[u].x; Bs[row * 33 + c4 + 1] = pb[u].y;
            Bs[row * 33 + c4 + 2] = pb[u].z; Bs[row * 33 + c4 + 3] = pb[u].w;
        }
        __syncthreads();
        if (ch < 7) {
            int k0 = (ch + 1) * 32;
            #pragma unroll
            for (int u = 0; u < 2; u++) {
                int idx = t + u * 256, row = idx >> 3, c4 = (idx & 7) * 4;
                pa[u] = *(const float4*)&g_all[(jb + row) * ND + k0 + c4];
                pb[u] = *(const float4*)&g_all[(kb + row) * ND + k0 + c4];
            }
        }
        #pragma unroll
        for (int dd = 0; dd < 32; dd++) {
            float a0 = As[(ty*4+0)*33 + dd], a1 = As[(ty*4+1)*33 + dd],
                  a2 = As[(ty*4+2)*33 + dd], a3 = As[(ty*4+3)*33 + dd];
            float b0 = Bs[(tx*4+0)*33 + dd], b1 = Bs[(tx*4+1)*33 + dd],
                  b2 = Bs[(tx*4+2)*33 + dd], b3 = Bs[(tx*4+3)*33 + dd];
            acc[0][0] = fmaf(a0,b0,acc[0][0]); acc[0][1] = fmaf(a0,b1,acc[0][1]);
            acc[0][2] = fmaf(a0,b2,acc[0][2]); acc[0][3] = fmaf(a0,b3,acc[0][3]);
            acc[1][0] = fmaf(a1,b0,acc[1][0]); acc[1][1] = fmaf(a1,b1,acc[1][1]);
            acc[1][2] = fmaf(a1,b2,acc[1][2]); acc[1][3] = fmaf(a1,b3,acc[1][3]);
            acc[2][0] = fmaf(a2,b0,acc[2][0]); acc[2][1] = fmaf(a2,b1,acc[2][1]);
            acc[2][2] = fmaf(a2,b2,acc[2][2]); acc[2][3] = fmaf(a2,b3,acc[2][3]);
            acc[3][0] = fmaf(a3,b0,acc[3][0]); acc[3][1] = fmaf(a3,b1,acc[3][1]);
            acc[3][2] = fmaf(a3,b2,acc[3][2]); acc[3][3] = fmaf(a3,b3,acc[3][3]);
        }
    }

    // exp + direct coalesced write
    float er[4][4];
    #pragma unroll
    for (int i = 0; i < 4; i++) {
        er[i][0] = expf(acc[i][0]); er[i][1] = expf(acc[i][1]);
        er[i][2] = expf(acc[i][2]); er[i][3] = expf(acc[i][3]);
        float4 r = make_float4(er[i][0], er[i][1], er[i][2], er[i][3]);
        *(float4*)&g_E[(jb + ty * 4 + i) * NM + kb + tx * 4] = r;
    }

    if (jt < 12) {
        if (jt != kt) {
            // mirror write via smem transpose (stride 65)
            __syncthreads();                 // done with As/Bs
            float* Tr = sbuf;                // 64*65 = 4160 <= 4224 floats
            #pragma unroll
            for (int i = 0; i < 4; i++)
                #pragma unroll
                for (int l = 0; l < 4; l++)
                    Tr[(tx * 4 + l) * 65 + ty * 4 + i] = er[i][l];
            __syncthreads();
            #pragma unroll
            for (int u = 0; u < 4; u++) {
                int idx = t + u * 256;       // 1024 float4 = 64 rows x 16
                int r = idx >> 4, c4 = (idx & 15) * 4;
                float4 v = make_float4(Tr[r*65 + c4], Tr[r*65 + c4 + 1],
                                       Tr[r*65 + c4 + 2], Tr[r*65 + c4 + 3]);
                *(float4*)&g_E[(kb + r) * NM + jb + c4] = v;
            }
        }
    } else {
        // anchor-row tile: accumulate masked Ea row sums (fixed-point, determ.)
        #pragma unroll
        for (int i = 0; i < 4; i++) {
            int b = ty * 4 + i;              // anchor index (48..63 = pad)
            float part = 0.f;
            if (b < NB) {
                int mb = lab[b];
                #pragma unroll
                for (int l = 0; l < 4; l++) {
                    int col = kb + tx * 4 + l;
                    if (lab[col >> 4] != mb) part += er[i][l];
                }
            }
            #pragma unroll
            for (int o = 8; o > 0; o >>= 1)
                part += __shfl_down_sync(0xffffffffu, part, o, 16);
            if (tx == 0 && b < NB)
                atomicAdd(&g_csum[b],
                          (unsigned long long)(long long)llrintf(part * SCALE_C));
        }
    }
}

// ------------- 2: warp-per-pair symmetric KL + in-kernel final reduction
// e=c*Et, a=c*Ea, t=e-a, mu=exp(e)-1 (series), d=mu-nu=t*h (series)
// symKL = 0.5*(Sdt*D1 - Sd*N1)/(D1*D2); D1=n+Smu, N1=St+Smut, D2=D1-Sd
__global__ void k_pairs(float* __restrict__ out) {
    __shared__ int lab[NB];
    __shared__ unsigned int ticket_s;
    int t = threadIdx.x, lane = t & 31, w = t >> 5;
    if (t < NB) lab[t] = g_lab[t];
    __syncthreads();
    int np = g_np;
    for (int p = blockIdx.x * 8 + w; p < np; p += PAIR_BLOCKS * 8) {
        int pr = g_pairs[p];
        int b = pr >> 16, j = pr & 0xffff;
        int mb = lab[b];
        float c = SCALE_C / (float)(long long)g_csum[b];
        const float* Et = g_E + j * NM;
        const float* Ea = g_E + (NM + b) * NM;

        float s0 = 0.f, s1 = 0.f, s2 = 0.f, s3 = 0.f, s4 = 0.f;
        #pragma unroll 4
        for (int i = 0; i < NM / 32; i++) {
            int k = i * 32 + lane;
            float m  = (lab[k >> 4] != mb) ? c : 0.f;   // zeroed lanes give 0 terms
            float e  = m * Et[k];
            float a  = m * Ea[k];
            float tt = e - a;
            float mu = e * (1.f + e * (0.5f + e * (1.f/6.f + e * (1.f/24.f))));
            float sp = e + a;
            float e2 = e * e, ea = e * a, a2 = a * a;
            float h  = 1.f + 0.5f * sp + (e2 + ea + a2) * (1.f/6.f)
                     + sp * (e2 + a2) * (1.f/24.f);
            float d  = tt * h;
            s0 += tt; s1 += mu; s2 = fmaf(mu, tt, s2);
            s3 += d;  s4 = fmaf(tt, d, s4);
        }
        #pragma unroll
        for (int o = 16; o > 0; o >>= 1) {
            s0 += __shfl_down_sync(0xffffffffu, s0, o);
            s1 += __shfl_down_sync(0xffffffffu, s1, o);
            s2 += __shfl_down_sync(0xffffffffu, s2, o);
            s3 += __shfl_down_sync(0xffffffffu, s3, o);
            s4 += __shfl_down_sync(0xffffffffu, s4, o);
        }
        if (lane == 0) {
            float n  = g_nneg[b];
            float D1 = n + s1;
            float N1 = s0 + s2;
            float D2 = D1 - s3;
            float kl = 0.5f * (s4 * D1 - s3 * N1) / (D1 * D2);
            atomicAdd(&g_rowsum[b],
                      (unsigned long long)(long long)llrintf(kl * SCALE_KL));
        }
    }
    // last block computes the final scalar (deterministic: integer sums)
    __threadfence();
    __syncthreads();
    if (t == 0) ticket_s = atomicAdd(&g_done, 1u);
    __syncthreads();
    if (ticket_s == PAIR_BLOCKS - 1 && t == 0) {
        float tot = 0.f;
        for (int b = 0; b < NB; b++) {
            float rs = (float)(long long)g_rowsum[b] * (1.f / SCALE_KL);
            tot += rs / g_P[b];
        }
        out[0] = tot / (float)NB;
    }
}

// ----------------------------------------------------------------- launch
extern "C" void kernel_launch(void* const* d_in, const int* in_sizes, int n_in,
                              void* d_out, int out_size) {
    const float* x     = (const float*)d_in[0];
    const int*   lab32 = (const int*)  d_in[1];
    float*       out   = (float*)      d_out;
    (void)in_sizes; (void)n_in; (void)out_size;

    k_prep <<<NR + 1, 256>>>(x, lab32);
    k_gemm <<<NTILES, 256>>>();
    k_pairs<<<PAIR_BLOCKS, 256>>>(out);
}

// round 8
// speedup vs baseline: 1.7557x; 1.6477x over previous
#include <cuda_runtime.h>

#define NB 48
#define NL 17
#define ND 256
#define NM 768    /* NB*(L-1) */
#define NR 832    /* NM + NB anchors = 13*64 */
#define PAIR_BLOCKS 768
#define NTILES 90 /* 78 upper-tri tok tiles + 12 anchor-row tiles */
#define NPB 144   /* pair-build blocks: 48*768/256 */

#define SCALE_C  4294967296.0f           /* 2^32 for csum fixed-point */
#define SCALE_KL 1.125899906842624e15f   /* 2^50 for kl fixed-point */

__device__ float g_all [NR*ND];   // rows 0..767 toks, 768..815 anchors, 816..831 zero
__device__ float g_E   [NR*NM];   // exp(sims): rows 0..767 Et (symmetric), 768..815 Ea
__device__ float g_nneg[NB];
__device__ float g_P   [NB];
__device__ int   g_lab [NB];
__device__ int   g_pairs[NB*NM];  // (b<<16)|j, unordered (consumers are order-free)
__device__ unsigned int       g_pcnt;        // zero-init; reset by k_pairs final block
__device__ unsigned long long g_csum  [NB];  // sum_neg Ea[b,k] * 2^32
__device__ unsigned long long g_rowsum[NB];  // sum_j kl[b,j]   * 2^50
__device__ unsigned int       g_done;

// ---------------------------------------------------------------- utilities
__device__ __forceinline__ float blockReduceSum(float v, volatile float* sm) {
    int lane = threadIdx.x & 31, wid = threadIdx.x >> 5;
    #pragma unroll
    for (int o = 16; o > 0; o >>= 1) v += __shfl_down_sync(0xffffffffu, v, o);
    if (lane == 0) sm[wid] = v;
    __syncthreads();
    if (threadIdx.x < 32) {
        float r = (threadIdx.x < 8) ? sm[threadIdx.x] : 0.f;
        #pragma unroll
        for (int o = 4; o > 0; o >>= 1) r += __shfl_down_sync(0xffffffffu, r, o);
        if (threadIdx.x == 0) sm[0] = r;
    }
    __syncthreads();
    float r = sm[0];
    __syncthreads();
    return r;
}

// Reference declares int64 labels; jax w/o x64 silently yields int32. An
// int64 buffer (values 0..7, little-endian) read as int32 is [v,0,v,0,...].
// Loads labels into shared lab[] (call with full block; does __syncthreads).
__device__ __forceinline__ void load_labels(const int* __restrict__ lab32,
                                            int* lab, int* flag) {
    int t = threadIdx.x;
    if (t == 0) {
        bool is64 = true;
        for (int i = 1; i < NB; i += 2) if (lab32[i] != 0) { is64 = false; break; }
        if (is64) for (int i = 0; i < NB; i += 2) {
            int v = lab32[i];
            if (v < 0 || v >= 8) { is64 = false; break; }
        }
        *flag = is64 ? 1 : 0;
    }
    __syncthreads();
    if (t < NB) lab[t] = (*flag) ? (int)((const long long*)lab32)[t] : lab32[t];
    __syncthreads();
}

// ---- 0: fully parallel prep.
// blocks 0..831: normalize/pad rows. blocks 832..975: build pair list.
// block 976: per-b scalars.
__global__ void k_prep(const float* __restrict__ x, const int* __restrict__ lab32) {
    int bid = blockIdx.x, t = threadIdx.x;
    if (bid < NR) {                       // normalize rows / zero pad
        __shared__ float red[32];
        int r = bid, d = t;
        if (r >= NB * NL) {
            g_all[(NM + r - NB * NL + NB) * ND + d] = 0.f;
            return;
        }
        float v = x[r * ND + d];
        float ss = blockReduceSum(v * v, red);
        float inv = 1.f / fmaxf(sqrtf(ss), 1e-12f);
        float xn = v * inv;
        int b = r / NL, p = r - b * NL;
        int row = (p == 0) ? (NM + b) : (b * (NL - 1) + p - 1);
        g_all[row * ND + d] = xn;
        return;
    }
    __shared__ int lab[NB];
    __shared__ int flag;
    load_labels(lab32, lab, &flag);
    if (bid < NR + NPB) {                 // pair list (unordered, atomic append)
        int p = (bid - NR) * 256 + t;     // 0..36863
        int b = p / NM, j = p - b * NM;
        if (lab[j >> 4] == lab[b]) {
            unsigned pos = atomicAdd(&g_pcnt, 1u);
            g_pairs[pos] = (b << 16) | j;
        }
        return;
    }
    // scalars
    if (t < NB) {
        int same = 0;
        #pragma unroll 8
        for (int o = 0; o < NB; o++) same += (lab[o] == lab[t]) ? 1 : 0;
        g_lab[t]  = lab[t];
        g_nneg[t] = (float)((NB - same) * (NL - 1));
        g_P[t]    = (float)(same * (NL - 1));
    }
}

// --------- 1: symmetric GEMM, exp epilogue, mirror write for off-diag tiles,
//              fused csum accumulation on anchor-row tiles (jt==12)
// tiles: id 0..77 -> (jt,kt) upper triangle of 12x12 tok grid; 78..89 -> (12,kt)
__global__ void k_gemm(void) {
    __shared__ float sbuf[2 * 64 * 33];
    __shared__ int lab[NB];
    float* As = sbuf;                 // [64][33]
    float* Bs = sbuf + 64 * 33;
    int t = threadIdx.x, tx = t & 15, ty = t >> 4;
    if (t < NB) lab[t] = g_lab[t];

    int id = blockIdx.x, jt, kt;
    if (id < 78) {
        jt = 0; int rem = id;
        while (rem >= 12 - jt) { rem -= 12 - jt; jt++; }
        kt = jt + rem;
    } else { jt = 12; kt = id - 78; }
    int jb = jt * 64, kb = kt * 64;

    // register prefetch of chunk 0
    float4 pa[2], pb[2];
    #pragma unroll
    for (int u = 0; u < 2; u++) {
        int idx = t + u * 256, row = idx >> 3, c4 = (idx & 7) * 4;
        pa[u] = *(const float4*)&g_all[(jb + row) * ND + c4];
        pb[u] = *(const float4*)&g_all[(kb + row) * ND + c4];
    }

    float acc[4][4] = {};
    for (int ch = 0; ch < 8; ch++) {
        __syncthreads();
        #pragma unroll
        for (int u = 0; u < 2; u++) {
            int idx = t + u * 256, row = idx >> 3, c4 = (idx & 7) * 4;
            As[row * 33 + c4 + 0] = pa[u].x; As[row * 33 + c4 + 1] = pa[u].y;
            As[row * 33 + c4 + 2] = pa[u].z; As[row * 33 + c4 + 3] = pa[u].w;
            Bs[row * 33 + c4 + 0] = pb[u].x; Bs[row * 33 + c4 + 1] = pb[u].y;
            Bs[row * 33 + c4 + 2] = pb[u].z; Bs[row * 33 + c4 + 3] = pb[u].w;
        }
        __syncthreads();
        if (ch < 7) {
            int k0 = (ch + 1) * 32;
            #pragma unroll
            for (int u = 0; u < 2; u++) {
                int idx = t + u * 256, row = idx >> 3, c4 = (idx & 7) * 4;
                pa[u] = *(const float4*)&g_all[(jb + row) * ND + k0 + c4];
                pb[u] = *(const float4*)&g_all[(kb + row) * ND + k0 + c4];
            }
        }
        #pragma unroll
        for (int dd = 0; dd < 32; dd++) {
            float a0 = As[(ty*4+0)*33 + dd], a1 = As[(ty*4+1)*33 + dd],
                  a2 = As[(ty*4+2)*33 + dd], a3 = As[(ty*4+3)*33 + dd];
            float b0 = Bs[(tx*4+0)*33 + dd], b1 = Bs[(tx*4+1)*33 + dd],
                  b2 = Bs[(tx*4+2)*33 + dd], b3 = Bs[(tx*4+3)*33 + dd];
            acc[0][0] = fmaf(a0,b0,acc[0][0]); acc[0][1] = fmaf(a0,b1,acc[0][1]);
            acc[0][2] = fmaf(a0,b2,acc[0][2]); acc[0][3] = fmaf(a0,b3,acc[0][3]);
            acc[1][0] = fmaf(a1,b0,acc[1][0]); acc[1][1] = fmaf(a1,b1,acc[1][1]);
            acc[1][2] = fmaf(a1,b2,acc[1][2]); acc[1][3] = fmaf(a1,b3,acc[1][3]);
            acc[2][0] = fmaf(a2,b0,acc[2][0]); acc[2][1] = fmaf(a2,b1,acc[2][1]);
            acc[2][2] = fmaf(a2,b2,acc[2][2]); acc[2][3] = fmaf(a2,b3,acc[2][3]);
            acc[3][0] = fmaf(a3,b0,acc[3][0]); acc[3][1] = fmaf(a3,b1,acc[3][1]);
            acc[3][2] = fmaf(a3,b2,acc[3][2]); acc[3][3] = fmaf(a3,b3,acc[3][3]);
        }
    }

    // exp + direct coalesced write
    float er[4][4];
    #pragma unroll
    for (int i = 0; i < 4; i++) {
        er[i][0] = expf(acc[i][0]); er[i][1] = expf(acc[i][1]);
        er[i][2] = expf(acc[i][2]); er[i][3] = expf(acc[i][3]);
        float4 r = make_float4(er[i][0], er[i][1], er[i][2], er[i][3]);
        *(float4*)&g_E[(jb + ty * 4 + i) * NM + kb + tx * 4] = r;
    }

    if (jt < 12) {
        if (jt != kt) {
            // mirror write via smem transpose (stride 65)
            __syncthreads();                 // done with As/Bs
            float* Tr = sbuf;                // 64*65 = 4160 <= 4224 floats
            #pragma unroll
            for (int i = 0; i < 4; i++)
                #pragma unroll
                for (int l = 0; l < 4; l++)
                    Tr[(tx * 4 + l) * 65 + ty * 4 + i] = er[i][l];
            __syncthreads();
            #pragma unroll
            for (int u = 0; u < 4; u++) {
                int idx = t + u * 256;       // 1024 float4 = 64 rows x 16
                int r = idx >> 4, c4 = (idx & 15) * 4;
                float4 v = make_float4(Tr[r*65 + c4], Tr[r*65 + c4 + 1],
                                       Tr[r*65 + c4 + 2], Tr[r*65 + c4 + 3]);
                *(float4*)&g_E[(kb + r) * NM + jb + c4] = v;
            }
        }
    } else {
        // anchor-row tile: accumulate masked Ea row sums (fixed-point, determ.)
        #pragma unroll
        for (int i = 0; i < 4; i++) {
            int b = ty * 4 + i;              // anchor index (48..63 = pad)
            float part = 0.f;
            if (b < NB) {
                int mb = lab[b];
                #pragma unroll
                for (int l = 0; l < 4; l++) {
                    int col = kb + tx * 4 + l;
                    if (lab[col >> 4] != mb) part += er[i][l];
                }
            }
            #pragma unroll
            for (int o = 8; o > 0; o >>= 1)
                part += __shfl_down_sync(0xffffffffu, part, o, 16);
            if (tx == 0 && b < NB)
                atomicAdd(&g_csum[b],
                          (unsigned long long)(long long)llrintf(part * SCALE_C));
        }
    }
}

// ------------- 2: warp-per-pair symmetric KL + in-kernel final reduction
// e=c*Et, a=c*Ea, t=e-a, mu=exp(e)-1 (series), d=mu-nu=t*h (series)
// symKL = 0.5*(Sdt*D1 - Sd*N1)/(D1*D2); D1=n+Smu, N1=St+Smut, D2=D1-Sd
// Pair order is irrelevant: per-pair kl is a pure function of globals and the
// accumulation is integer fixed-point -> bit-identical across replays.
__global__ void k_pairs(float* __restrict__ out) {
    __shared__ int lab[NB];
    __shared__ unsigned int ticket_s;
    int t = threadIdx.x, lane = t & 31, w = t >> 5;
    if (t < NB) lab[t] = g_lab[t];
    __syncthreads();
    int np = (int)g_pcnt;
    for (int p = blockIdx.x * 8 + w; p < np; p += PAIR_BLOCKS * 8) {
        int pr = g_pairs[p];
        int b = pr >> 16, j = pr & 0xffff;
        int mb = lab[b];
        float c = SCALE_C / (float)(long long)g_csum[b];
        const float* Et = g_E + j * NM;
        const float* Ea = g_E + (NM + b) * NM;

        float s0 = 0.f, s1 = 0.f, s2 = 0.f, s3 = 0.f, s4 = 0.f;
        #pragma unroll 4
        for (int i = 0; i < NM / 32; i++) {
            int k = i * 32 + lane;
            float m  = (lab[k >> 4] != mb) ? c : 0.f;   // zeroed lanes give 0 terms
            float e  = m * Et[k];
            float a  = m * Ea[k];
            float tt = e - a;
            float mu = e * (1.f + e * (0.5f + e * (1.f/6.f + e * (1.f/24.f))));
            float sp = e + a;
            float e2 = e * e, ea = e * a, a2 = a * a;
            float h  = 1.f + 0.5f * sp + (e2 + ea + a2) * (1.f/6.f)
                     + sp * (e2 + a2) * (1.f/24.f);
            float d  = tt * h;
            s0 += tt; s1 += mu; s2 = fmaf(mu, tt, s2);
            s3 += d;  s4 = fmaf(tt, d, s4);
        }
        #pragma unroll
        for (int o = 16; o > 0; o >>= 1) {
            s0 += __shfl_down_sync(0xffffffffu, s0, o);
            s1 += __shfl_down_sync(0xffffffffu, s1, o);
            s2 += __shfl_down_sync(0xffffffffu, s2, o);
            s3 += __shfl_down_sync(0xffffffffu, s3, o);
            s4 += __shfl_down_sync(0xffffffffu, s4, o);
        }
        if (lane == 0) {
            float n  = g_nneg[b];
            float D1 = n + s1;
            float N1 = s0 + s2;
            float D2 = D1 - s3;
            float kl = 0.5f * (s4 * D1 - s3 * N1) / (D1 * D2);
            atomicAdd(&g_rowsum[b],
                      (unsigned long long)(long long)llrintf(kl * SCALE_KL));
        }
    }
    // last block: final scalar + reset all counters for the next graph replay
    __threadfence();
    __syncthreads();
    if (t == 0) ticket_s = atomicAdd(&g_done, 1u);
    __syncthreads();
    if (ticket_s == PAIR_BLOCKS - 1 && t == 0) {
        float tot = 0.f;
        for (int b = 0; b < NB; b++) {
            float rs = (float)(long long)g_rowsum[b] * (1.f / SCALE_KL);
            tot += rs / g_P[b];
            g_rowsum[b] = 0ull;
            g_csum[b]   = 0ull;
        }
        out[0] = tot / (float)NB;
        g_pcnt = 0u;
        g_done = 0u;
    }
}

// ----------------------------------------------------------------- launch
extern "C" void kernel_launch(void* const* d_in, const int* in_sizes, int n_in,
                              void* d_out, int out_size) {
    const float* x     = (const float*)d_in[0];
    const int*   lab32 = (const int*)  d_in[1];
    float*       out   = (float*)      d_out;
    (void)in_sizes; (void)n_in; (void)out_size;

    k_prep <<<NR + NPB + 1, 256>>>(x, lab32);
    k_gemm <<<NTILES, 256>>>();
    k_pairs<<<PAIR_BLOCKS, 256>>>(out);
}